// round 15
// baseline (speedup 1.0000x reference)
#include <cuda_runtime.h>
#include <cuda_fp16.h>
#include <math.h>

// Problem constants (fixed shapes from reference)
#define BB 16
#define SS 4096
#define DD 64
#define HH 8
#define NBK 64          // buckets per hash round
#define CHK 512         // chunks per batch (HH * NBK)
#define BSZ 64          // bucket/chunk size
#define KVN 128         // keys per chunk (current + look-back)

// -------------------- device scratch (no allocation allowed) --------------------
__device__ int     g_buckets[BB * HH * SS];               // 2 MB
__device__ int     g_st[BB * HH * SS];                    // 2 MB  sorted original positions
__device__ float   g_lse[BB * SS * HH];                   // 2 MB  logits, [b][t][h]
__device__ __half2 g_o[(size_t)BB * SS * HH * 32];        // 67 MB outputs (fp16), [b][t][h][32]
__device__ float   g_qs[BB * SS];                         // 256 KB  0.125 * ||qk row||
__device__ __half2 g_kh[(size_t)BB * SS * 32];            // 8 MB  fp16 normalized k
__device__ __half2 g_vh[(size_t)BB * SS * 32];            // 8 MB  fp16 v

// -------------------- helpers --------------------
__device__ __forceinline__ unsigned h2_u32(__half2 h) {
    union { __half2 h; unsigned u; } cvt;
    cvt.h = h;
    return cvt.u;
}

__device__ __forceinline__ void mma_f16(float* c,
                                        unsigned a0, unsigned a1, unsigned a2, unsigned a3,
                                        unsigned b0, unsigned b1) {
    asm volatile("mma.sync.aligned.m16n8k16.row.col.f32.f16.f16.f32 "
                 "{%0,%1,%2,%3},{%4,%5,%6,%7},{%8,%9},{%0,%1,%2,%3};"
                 : "+f"(c[0]), "+f"(c[1]), "+f"(c[2]), "+f"(c[3])
                 : "r"(a0), "r"(a1), "r"(a2), "r"(a3), "r"(b0), "r"(b1));
}

__device__ __forceinline__ void ldsm4(unsigned& r0, unsigned& r1, unsigned& r2, unsigned& r3,
                                      unsigned addr) {
    asm volatile("ldmatrix.sync.aligned.m8n8.x4.shared.b16 {%0,%1,%2,%3}, [%4];"
                 : "=r"(r0), "=r"(r1), "=r"(r2), "=r"(r3) : "r"(addr));
}

__device__ __forceinline__ void ldsm4t(unsigned& r0, unsigned& r1, unsigned& r2, unsigned& r3,
                                       unsigned addr) {
    asm volatile("ldmatrix.sync.aligned.m8n8.x4.trans.shared.b16 {%0,%1,%2,%3}, [%4];"
                 : "=r"(r0), "=r"(r1), "=r"(r2), "=r"(r3) : "r"(addr));
}

__device__ __forceinline__ void cp16(unsigned dst, const void* src) {
    asm volatile("cp.async.cg.shared.global [%0], [%1], 16;" :: "r"(dst), "l"(src) : "memory");
}

// packed f32x2 helpers (Blackwell)
__device__ __forceinline__ unsigned long long pack2(float x, float y) {
    unsigned long long r;
    asm("mov.b64 %0, {%1, %2};" : "=l"(r) : "f"(x), "f"(y));
    return r;
}
__device__ __forceinline__ void unpack2(float& x, float& y, unsigned long long p) {
    asm("mov.b64 {%0, %1}, %2;" : "=f"(x), "=f"(y) : "l"(p));
}
__device__ __forceinline__ void fma2(unsigned long long& d, unsigned long long a, unsigned long long b) {
    asm("fma.rn.f32x2 %0, %1, %2, %0;" : "+l"(d) : "l"(a), "l"(b));
}

// row-group barrier: warps {wq, wq+2, wq+4, wq+6} (128 threads), ids 1..2
#define BARG(id) asm volatile("bar.sync %0, 128;" :: "r"(id) : "memory")

// ==================== Kernel 1: LSH hashing (fp32 f32x2) + fused fp16 prep ====================
// grid = BB * (SS/64) = 1024 CTAs, 256 threads.
__global__ __launch_bounds__(256, 2) void hash_kernel(const float* __restrict__ qk,
                                                      const float* __restrict__ v,
                                                      const float* __restrict__ rot) {
    extern __shared__ float sm[];
    float* qT  = sm;              // 64*68 floats
    float* big = sm + 64 * 68;    // max(64*260, 256*68) = 17408 floats

    const int blk  = blockIdx.x;
    const int b    = blk >> 6;
    const int t0   = (blk & 63) * 64;
    const int tid  = threadIdx.x;
    const int w    = tid >> 5, l = tid & 31;

    {
        const float4* rg = (const float4*)rot;
        for (int i4 = tid; i4 < 64 * 64; i4 += 256) {
            int f = i4 >> 6, o4 = i4 & 63;
            *(float4*)&big[f * 260 + o4 * 4] = rg[i4];
        }
    }
    // q tile load (transposed into qT) + fused prep: qs, kh, vh
    for (int r = 0; r < 8; r++) {
        int i = w * 8 + r;
        size_t gi = (size_t)b * SS + t0 + i;
        float2 qv = ((const float2*)(qk + gi * DD))[l];
        qT[(2 * l) * 68 + i]     = qv.x;
        qT[(2 * l + 1) * 68 + i] = qv.y;
        float ssq = qv.x * qv.x + qv.y * qv.y;
#pragma unroll
        for (int o = 16; o; o >>= 1) ssq += __shfl_xor_sync(0xffffffffu, ssq, o);
        float nrm = sqrtf(ssq);
        float inv = 1.0f / fmaxf(nrm, 1e-12f);
        g_kh[gi * 32 + l] = __floats2half2_rn(qv.x * inv, qv.y * inv);
        if (l == 0) g_qs[gi] = 0.125f * nrm;
        float2 vv = ((const float2*)(v + gi * DD))[l];
        g_vh[gi * 32 + l] = __floats2half2_rn(vv.x, vv.y);
    }
    __syncthreads();

    const int rt = tid >> 4, ct = tid & 15;
    unsigned long long acc2[4][8];
#pragma unroll
    for (int r = 0; r < 4; r++)
#pragma unroll
        for (int p = 0; p < 8; p++) acc2[r][p] = pack2(0.f, 0.f);

    const float4* qT4 = (const float4*)qT;   // stride 17
    const float4* rt4 = (const float4*)big;  // stride 65
#pragma unroll 4
    for (int f = 0; f < 64; f++) {
        float4 q = qT4[f * 17 + rt];
        unsigned long long qq[4];
        qq[0] = pack2(q.x, q.x); qq[1] = pack2(q.y, q.y);
        qq[2] = pack2(q.z, q.z); qq[3] = pack2(q.w, q.w);
#pragma unroll
        for (int g = 0; g < 4; g++) {
            float4 rv = rt4[f * 65 + g * 16 + ct];
            unsigned long long r0 = pack2(rv.x, rv.y);
            unsigned long long r1 = pack2(rv.z, rv.w);
#pragma unroll
            for (int r = 0; r < 4; r++) {
                fma2(acc2[r][g * 2],     qq[r], r0);
                fma2(acc2[r][g * 2 + 1], qq[r], r1);
            }
        }
    }
    float acc[4][16];
#pragma unroll
    for (int r = 0; r < 4; r++)
#pragma unroll
        for (int p = 0; p < 8; p++)
            unpack2(acc[r][p * 2], acc[r][p * 2 + 1], acc2[r][p]);
    __syncthreads();   // rot dead, reuse region as dsH[o][t] stride 68

    float* dsH = big;
#pragma unroll
    for (int g = 0; g < 4; g++)
#pragma unroll
        for (int c = 0; c < 4; c++) {
            int o = g * 64 + ct * 4 + c;
            *(float4*)&dsH[o * 68 + rt * 4] =
                make_float4(acc[0][g * 4 + c], acc[1][g * 4 + c], acc[2][g * 4 + c], acc[3][g * 4 + c]);
        }
    __syncthreads();

    for (int p = tid; p < 512; p += 256) {
        int t = p & 63, hh = p >> 6;
        const float* dv = &dsH[(hh * 32) * 68 + t];
        float best = dv[0];
        int bi = 0;
#pragma unroll
        for (int j = 1; j < 32; j++) { float vv = dv[j * 68];  if (vv > best) { best = vv; bi = j; } }
#pragma unroll
        for (int j = 0; j < 32; j++) { float vv = -dv[j * 68]; if (vv > best) { best = vv; bi = 32 + j; } }
        g_buckets[((size_t)(b * HH + hh)) * SS + t0 + t] = bi;
    }
}

// ==================== Kernel 2: stable counting sort per (b,h) ====================
__global__ __launch_bounds__(512) void sort_kernel() {
    __shared__ int hist[16][64];
    __shared__ int run[16][64];
    __shared__ int totals[64];
    __shared__ int bstart[64];

    const int bh  = blockIdx.x;
    const int* bk = g_buckets + (size_t)bh * SS;
    int* dst      = g_st + (size_t)bh * SS;
    const int tid = threadIdx.x, w = tid >> 5, l = tid & 31;

    for (int i = tid; i < 1024; i += 512) ((int*)hist)[i] = 0;
    __syncthreads();

    for (int r = 0; r < 8; r++) {
        int t = w * 256 + r * 32 + l;
        int vv = bk[t];
        unsigned mask = __match_any_sync(0xffffffffu, vv);
        if (l == (int)(__ffs(mask) - 1)) hist[w][vv] += __popc(mask);
        __syncwarp();
    }
    __syncthreads();

    if (tid < 64) {
        int s = 0;
        for (int ww = 0; ww < 16; ww++) { int tmp = hist[ww][tid]; hist[ww][tid] = s; s += tmp; }
        totals[tid] = s;
    }
    __syncthreads();
    if (tid == 0) {
        int s = 0;
        for (int vv = 0; vv < 64; vv++) { bstart[vv] = s; s += totals[vv]; }
    }
    __syncthreads();
    for (int i = tid; i < 1024; i += 512) {
        int ww = i >> 6, vv = i & 63;
        run[ww][vv] = bstart[vv] + hist[ww][vv];
    }
    __syncthreads();

    for (int r = 0; r < 8; r++) {
        int t = w * 256 + r * 32 + l;
        int vv = bk[t];
        unsigned mask = __match_any_sync(0xffffffffu, vv);
        int rank = __popc(mask & ((1u << l) - 1u));
        int base = run[w][vv];
        __syncwarp();
        if (l == (int)(__ffs(mask) - 1)) run[w][vv] = base + __popc(mask);
        __syncwarp();
        dst[base + rank] = t;
    }
}

// ==================== Kernel 3: chunked attention (Gram, 2x4 retile, two-phase PV) ====================
// grid = BB*CHK = 8192 CTAs, 256 threads (8 warps), 55040B smem, 4 CTAs/SM.
// Warp (wq, wk): wq = w&1 rows [wq*32,+32), wk = w>>1 keys [wk*32,+32).
// Smem: tki[128]@0 | qs[64]f@512 | stats float2[4*64]@768 | Ksm 128x144B@2816
//       Vsm 128x144B@21248 | Dxh half[3][64][40]@39680
__global__ __launch_bounds__(256, 4) void attn_kernel() {
    extern __shared__ char smc[];
    int*    tki   = (int*)smc;
    float*  qs_sm = (float*)(smc + 512);
    float2* stat2 = (float2*)(smc + 768);        // [wk*64 + row]
    __half* Ksm   = (__half*)(smc + 2816);
    __half* Vsm   = (__half*)(smc + 21248);
    __half* Dxh   = (__half*)(smc + 39680);      // [3][64][40]

    const int blk = blockIdx.x;
    const int b = blk >> 9, c = blk & 511;
    const int h  = c >> 6;
    const int cp = (c + 511) & 511;
    const int hp = cp >> 6;
    const int tid = threadIdx.x, w = tid >> 5, l = tid & 31;
    const int gID = l >> 2, tig = l & 3;
    const int wq = w & 1, wk = w >> 1;
    const int rb = wq * 32;

    if (tid < 64) {
        int t = g_st[((size_t)(b * HH + h)) * SS + (c & 63) * 64 + tid];
        tki[tid] = t;
        qs_sm[tid] = g_qs[(size_t)b * SS + t];
    } else if (tid < 128) {
        int i = tid - 64;
        tki[64 + i] = g_st[((size_t)(b * HH + hp)) * SS + (cp & 63) * 64 + i];
    }
    __syncthreads();

    // ---- gather K, V via cp.async: 16B chunks, 8 per 128B row
    {
        unsigned k_u32 = (unsigned)__cvta_generic_to_shared(Ksm);
        unsigned v_u32 = (unsigned)__cvta_generic_to_shared(Vsm);
        const char* kh = (const char*)g_kh + (size_t)b * SS * 128;
        const char* vh = (const char*)g_vh + (size_t)b * SS * 128;
#pragma unroll
        for (int it = 0; it < 4; it++) {
            int slot = tid + it * 256;
            int row = slot >> 3, ch = slot & 7;
            cp16(k_u32 + row * 144 + ch * 16, kh + (size_t)tki[row] * 128 + ch * 16);
        }
#pragma unroll
        for (int it = 0; it < 4; it++) {
            int slot = tid + it * 256;
            int row = slot >> 3, ch = slot & 7;
            cp16(v_u32 + row * 144 + ch * 16, vh + (size_t)tki[row] * 128 + ch * 16);
        }
        asm volatile("cp.async.commit_group;" ::: "memory");
        asm volatile("cp.async.wait_group 0;" ::: "memory");
    }
    __syncthreads();

    // ---- ldmatrix lane addressing
    const int lrow = (l & 7) + ((l >> 3) & 1) * 8;
    const int lcsh = ((l >> 4) & 1) * 16;
    const unsigned ksm_u32 = (unsigned)__cvta_generic_to_shared(Ksm);
    const unsigned afrag0 = ksm_u32 + (rb + lrow) * 144 + lcsh;        // A m-tile 0
    const unsigned afrag1 = ksm_u32 + (rb + 16 + lrow) * 144 + lcsh;   // A m-tile 1
    const unsigned kfragb = ksm_u32 + (wk * 32 + lrow) * 144 + lcsh;
    const unsigned vfragb = (unsigned)__cvta_generic_to_shared(Vsm) + (wk * 32 + lrow) * 144 + lcsh;

    // ---- QK (Gram): rows [rb,+32), keys [wk*32,+32), K=64
    float cqk[2][4][4];
#pragma unroll
    for (int mt = 0; mt < 2; mt++)
#pragma unroll
        for (int nt = 0; nt < 4; nt++)
#pragma unroll
            for (int r = 0; r < 4; r++) cqk[mt][nt][r] = 0.f;

#pragma unroll
    for (int s = 0; s < 4; s++) {
        unsigned aA[2][4];
        ldsm4(aA[0][0], aA[0][1], aA[0][2], aA[0][3], afrag0 + s * 32);
        ldsm4(aA[1][0], aA[1][1], aA[1][2], aA[1][3], afrag1 + s * 32);
#pragma unroll
        for (int g = 0; g < 2; g++) {
            unsigned b00, b01, b10, b11;
            ldsm4(b00, b01, b10, b11, kfragb + g * 16 * 144 + s * 32);
#pragma unroll
            for (int mt = 0; mt < 2; mt++) {
                mma_f16(cqk[mt][2 * g],     aA[mt][0], aA[mt][1], aA[mt][2], aA[mt][3], b00, b10);
                mma_f16(cqk[mt][2 * g + 1], aA[mt][0], aA[mt][1], aA[mt][2], aA[mt][3], b01, b11);
            }
        }
    }

    // ---- per-row scale, self-mask
    float qsv[2][2];
    int   tqv[2][2];
#pragma unroll
    for (int mt = 0; mt < 2; mt++) {
        qsv[mt][0] = qs_sm[rb + mt * 16 + gID];
        qsv[mt][1] = qs_sm[rb + mt * 16 + gID + 8];
        tqv[mt][0] = tki[rb + mt * 16 + gID];
        tqv[mt][1] = tki[rb + mt * 16 + gID + 8];
    }
#pragma unroll
    for (int nt = 0; nt < 4; nt++) {
        int2 kk = *(int2*)&tki[wk * 32 + nt * 8 + 2 * tig];
#pragma unroll
        for (int mt = 0; mt < 2; mt++) {
            float* cc = cqk[mt][nt];
            cc[0] *= qsv[mt][0]; cc[1] *= qsv[mt][0];
            cc[2] *= qsv[mt][1]; cc[3] *= qsv[mt][1];
            if (kk.x == tqv[mt][0]) cc[0] = -5e4f;
            if (kk.y == tqv[mt][0]) cc[1] = -5e4f;
            if (kk.x == tqv[mt][1]) cc[2] = -5e4f;
            if (kk.y == tqv[mt][1]) cc[3] = -5e4f;
        }
    }

    // ---- softmax partials over this warp's 32 cols
    float mm[2][2], ss[2][2];
#pragma unroll
    for (int mt = 0; mt < 2; mt++)
#pragma unroll
        for (int rh = 0; rh < 2; rh++) { mm[mt][rh] = -3.4e38f; ss[mt][rh] = 0.f; }
#pragma unroll
    for (int mt = 0; mt < 2; mt++)
#pragma unroll
        for (int nt = 0; nt < 4; nt++) {
            mm[mt][0] = fmaxf(mm[mt][0], fmaxf(cqk[mt][nt][0], cqk[mt][nt][1]));
            mm[mt][1] = fmaxf(mm[mt][1], fmaxf(cqk[mt][nt][2], cqk[mt][nt][3]));
        }
#pragma unroll
    for (int mt = 0; mt < 2; mt++)
#pragma unroll
        for (int rh = 0; rh < 2; rh++) {
            mm[mt][rh] = fmaxf(mm[mt][rh], __shfl_xor_sync(0xffffffffu, mm[mt][rh], 1));
            mm[mt][rh] = fmaxf(mm[mt][rh], __shfl_xor_sync(0xffffffffu, mm[mt][rh], 2));
        }
#pragma unroll
    for (int mt = 0; mt < 2; mt++)
#pragma unroll
        for (int nt = 0; nt < 4; nt++) {
            float* cc = cqk[mt][nt];
            cc[0] = __expf(cc[0] - mm[mt][0]); cc[1] = __expf(cc[1] - mm[mt][0]);
            cc[2] = __expf(cc[2] - mm[mt][1]); cc[3] = __expf(cc[3] - mm[mt][1]);
            ss[mt][0] += cc[0] + cc[1];
            ss[mt][1] += cc[2] + cc[3];
        }
#pragma unroll
    for (int mt = 0; mt < 2; mt++)
#pragma unroll
        for (int rh = 0; rh < 2; rh++) {
            ss[mt][rh] += __shfl_xor_sync(0xffffffffu, ss[mt][rh], 1);
            ss[mt][rh] += __shfl_xor_sync(0xffffffffu, ss[mt][rh], 2);
        }
    if (tig == 0) {
#pragma unroll
        for (int mt = 0; mt < 2; mt++) {
            stat2[wk * 64 + rb + mt * 16 + gID]     = make_float2(mm[mt][0], ss[mt][0]);
            stat2[wk * 64 + rb + mt * 16 + gID + 8] = make_float2(mm[mt][1], ss[mt][1]);
        }
    }
    BARG(1 + wq);

    // ---- 4-way merge, per-row scale factors
    float sc[2][2];
#pragma unroll
    for (int mt = 0; mt < 2; mt++)
#pragma unroll
        for (int rh = 0; rh < 2; rh++) {
            int row = rb + mt * 16 + gID + rh * 8;
            float2 p0 = stat2[0 * 64 + row], p1 = stat2[1 * 64 + row];
            float2 p2 = stat2[2 * 64 + row], p3 = stat2[3 * 64 + row];
            float M = fmaxf(fmaxf(p0.x, p1.x), fmaxf(p2.x, p3.x));
            float S = p0.y * __expf(p0.x - M) + p1.y * __expf(p1.x - M)
                    + p2.y * __expf(p2.x - M) + p3.y * __expf(p3.x - M);
            sc[mt][rh] = __expf(mm[mt][rh] - M) / S;
            if (wk == 0 && tig == 0)
                g_lse[((size_t)b * SS + tki[row]) * HH + h] = M + __logf(S);
        }

    // ---- PV A-fragments (P in fp16); cqk dies
    unsigned af[2][2][4];   // [mt][ks][reg], ks over this warp's 32 keys
#pragma unroll
    for (int mt = 0; mt < 2; mt++)
#pragma unroll
        for (int s = 0; s < 2; s++) {
            af[mt][s][0] = h2_u32(__floats2half2_rn(cqk[mt][2 * s][0] * sc[mt][0], cqk[mt][2 * s][1] * sc[mt][0]));
            af[mt][s][1] = h2_u32(__floats2half2_rn(cqk[mt][2 * s][2] * sc[mt][1], cqk[mt][2 * s][3] * sc[mt][1]));
            af[mt][s][2] = h2_u32(__floats2half2_rn(cqk[mt][2 * s + 1][0] * sc[mt][0], cqk[mt][2 * s + 1][1] * sc[mt][0]));
            af[mt][s][3] = h2_u32(__floats2half2_rn(cqk[mt][2 * s + 1][2] * sc[mt][1], cqk[mt][2 * s + 1][3] * sc[mt][1]));
        }

    // ---- PV in two f-phases of 32; 4-way key reduction via Dxh
#pragma unroll
    for (int ph = 0; ph < 2; ph++) {
        float oacc[2][4][4];
#pragma unroll
        for (int mt = 0; mt < 2; mt++)
#pragma unroll
            for (int ft = 0; ft < 4; ft++)
#pragma unroll
                for (int r = 0; r < 4; r++) oacc[mt][ft][r] = 0.f;

#pragma unroll
        for (int s = 0; s < 2; s++) {
#pragma unroll
            for (int t = 0; t < 2; t++) {
                unsigned r0, r1, r2, r3;
                ldsm4t(r0, r1, r2, r3, vfragb + s * 16 * 144 + ph * 64 + t * 32);
#pragma unroll
                for (int mt = 0; mt < 2; mt++) {
                    mma_f16(oacc[mt][2 * t],     af[mt][s][0], af[mt][s][1], af[mt][s][2], af[mt][s][3], r0, r1);
                    mma_f16(oacc[mt][2 * t + 1], af[mt][s][0], af[mt][s][1], af[mt][s][2], af[mt][s][3], r2, r3);
                }
            }
        }

        if (wk > 0) {
            __half* dst = Dxh + (wk - 1) * 64 * 40;
#pragma unroll
            for (int mt = 0; mt < 2; mt++)
#pragma unroll
                for (int ft = 0; ft < 4; ft++) {
                    int row = rb + mt * 16 + gID;
                    *(__half2*)&dst[row * 40 + ft * 8 + 2 * tig]       = __floats2half2_rn(oacc[mt][ft][0], oacc[mt][ft][1]);
                    *(__half2*)&dst[(row + 8) * 40 + ft * 8 + 2 * tig] = __floats2half2_rn(oacc[mt][ft][2], oacc[mt][ft][3]);
                }
        }
        BARG(1 + wq);
        if (wk == 0) {
#pragma unroll
            for (int mt = 0; mt < 2; mt++) {
                int row0 = rb + mt * 16 + gID;
                __half2* o0 = g_o + (((size_t)b * SS + tki[row0]) * HH + h) * 32;
                __half2* o1 = g_o + (((size_t)b * SS + tki[row0 + 8]) * HH + h) * 32;
#pragma unroll
                for (int ft = 0; ft < 4; ft++) {
                    float a0 = oacc[mt][ft][0], a1 = oacc[mt][ft][1];
                    float a2 = oacc[mt][ft][2], a3 = oacc[mt][ft][3];
#pragma unroll
                    for (int j = 0; j < 3; j++) {
                        const __half* src = Dxh + j * 64 * 40;
                        float2 d0 = __half22float2(*(__half2*)&src[row0 * 40 + ft * 8 + 2 * tig]);
                        float2 d1 = __half22float2(*(__half2*)&src[(row0 + 8) * 40 + ft * 8 + 2 * tig]);
                        a0 += d0.x; a1 += d0.y;
                        a2 += d1.x; a3 += d1.y;
                    }
                    o0[ph * 16 + ft * 4 + tig] = __floats2half2_rn(a0, a1);
                    o1[ph * 16 + ft * 4 + tig] = __floats2half2_rn(a2, a3);
                }
            }
        }
        BARG(1 + wq);   // Dxh reusable for next phase
    }
}

// ==================== Kernel 4: combine hash rounds ([b][t][h] contiguous) ====================
__global__ __launch_bounds__(256) void combine_kernel(float* __restrict__ out) {
    const int gw = (blockIdx.x * 256 + threadIdx.x) >> 5;
    const int l  = threadIdx.x & 31;
    const int b  = gw >> 12, t = gw & (SS - 1);

    const float* lsep = g_lse + ((size_t)b * SS + t) * HH;
    float lg[HH];
#pragma unroll
    for (int hh = 0; hh < HH; hh++) lg[hh] = lsep[hh];
    float m = lg[0];
#pragma unroll
    for (int hh = 1; hh < HH; hh++) m = fmaxf(m, lg[hh]);
    float wv[HH];
    float wsum = 0.f;
#pragma unroll
    for (int hh = 0; hh < HH; hh++) { wv[hh] = __expf(lg[hh] - m); wsum += wv[hh]; }
    float inv = 1.0f / wsum;

    const __half2* ob = g_o + ((size_t)b * SS + t) * HH * 32;
    float2 accv = make_float2(0.f, 0.f);
#pragma unroll
    for (int hh = 0; hh < HH; hh++) {
        float2 ov = __half22float2(ob[hh * 32 + l]);
        float wgt = wv[hh] * inv;
        accv.x += wgt * ov.x;
        accv.y += wgt * ov.y;
    }
    ((float2*)(out + ((size_t)b * SS + t) * DD))[l] = accv;
}

// ==================== launch ====================
extern "C" void kernel_launch(void* const* d_in, const int* in_sizes, int n_in,
                              void* d_out, int out_size) {
    const float* qk  = (const float*)d_in[0];
    const float* v   = (const float*)d_in[1];
    const float* rot = (const float*)d_in[2];
    float* out = (float*)d_out;

    (void)in_sizes; (void)n_in; (void)out_size;

    const int hash_smem = 87040;   // 64*68*4 + 256*68*4
    const int attn_smem = 55040;   // tki/qs/stats + Ksm + Vsm + Dxh[3][64][40]
    cudaFuncSetAttribute(hash_kernel, cudaFuncAttributeMaxDynamicSharedMemorySize, hash_smem);
    cudaFuncSetAttribute(attn_kernel, cudaFuncAttributeMaxDynamicSharedMemorySize, attn_smem);

    hash_kernel<<<BB * (SS / 64), 256, hash_smem>>>(qk, v, rot);
    sort_kernel<<<BB * HH, 512>>>();
    attn_kernel<<<BB * CHK, 256, attn_smem>>>();
    combine_kernel<<<(BB * SS) / 8, 256>>>(out);
}

// round 16
// speedup vs baseline: 1.0971x; 1.0971x over previous
#include <cuda_runtime.h>
#include <cuda_fp16.h>
#include <math.h>

// Problem constants (fixed shapes from reference)
#define BB 16
#define SS 4096
#define DD 64
#define HH 8
#define NBK 64          // buckets per hash round
#define CHK 512         // chunks per batch (HH * NBK)
#define BSZ 64          // bucket/chunk size
#define KVN 128         // keys per chunk (current + look-back)

// -------------------- device scratch (no allocation allowed) --------------------
__device__ int     g_buckets[BB * HH * SS];               // 2 MB
__device__ int     g_st[BB * HH * SS];                    // 2 MB  sorted original positions
__device__ float   g_lse[BB * SS * HH];                   // 2 MB  logits, [b][t][h]
__device__ __half2 g_o[(size_t)BB * SS * HH * 32];        // 67 MB outputs (fp16), [b][t][h][32]
__device__ float   g_qs[BB * SS];                         // 256 KB  0.125*log2e * ||qk row||
__device__ __half2 g_kh[(size_t)BB * SS * 32];            // 8 MB  fp16 normalized k
__device__ __half2 g_vh[(size_t)BB * SS * 32];            // 8 MB  fp16 v

// -------------------- helpers --------------------
__device__ __forceinline__ unsigned h2_u32(__half2 h) {
    union { __half2 h; unsigned u; } cvt;
    cvt.h = h;
    return cvt.u;
}

__device__ __forceinline__ float ex2f(float x) {
    float r;
    asm("ex2.approx.ftz.f32 %0, %1;" : "=f"(r) : "f"(x));
    return r;
}

__device__ __forceinline__ void mma_f16(float* c,
                                        unsigned a0, unsigned a1, unsigned a2, unsigned a3,
                                        unsigned b0, unsigned b1) {
    asm volatile("mma.sync.aligned.m16n8k16.row.col.f32.f16.f16.f32 "
                 "{%0,%1,%2,%3},{%4,%5,%6,%7},{%8,%9},{%0,%1,%2,%3};"
                 : "+f"(c[0]), "+f"(c[1]), "+f"(c[2]), "+f"(c[3])
                 : "r"(a0), "r"(a1), "r"(a2), "r"(a3), "r"(b0), "r"(b1));
}

__device__ __forceinline__ void ldsm4(unsigned& r0, unsigned& r1, unsigned& r2, unsigned& r3,
                                      unsigned addr) {
    asm volatile("ldmatrix.sync.aligned.m8n8.x4.shared.b16 {%0,%1,%2,%3}, [%4];"
                 : "=r"(r0), "=r"(r1), "=r"(r2), "=r"(r3) : "r"(addr));
}

__device__ __forceinline__ void ldsm4t(unsigned& r0, unsigned& r1, unsigned& r2, unsigned& r3,
                                       unsigned addr) {
    asm volatile("ldmatrix.sync.aligned.m8n8.x4.trans.shared.b16 {%0,%1,%2,%3}, [%4];"
                 : "=r"(r0), "=r"(r1), "=r"(r2), "=r"(r3) : "r"(addr));
}

__device__ __forceinline__ void cp16(unsigned dst, const void* src) {
    asm volatile("cp.async.cg.shared.global [%0], [%1], 16;" :: "r"(dst), "l"(src) : "memory");
}

// packed f32x2 helpers (Blackwell)
__device__ __forceinline__ unsigned long long pack2(float x, float y) {
    unsigned long long r;
    asm("mov.b64 %0, {%1, %2};" : "=l"(r) : "f"(x), "f"(y));
    return r;
}
__device__ __forceinline__ void unpack2(float& x, float& y, unsigned long long p) {
    asm("mov.b64 {%0, %1}, %2;" : "=f"(x), "=f"(y) : "l"(p));
}
__device__ __forceinline__ void fma2(unsigned long long& d, unsigned long long a, unsigned long long b) {
    asm("fma.rn.f32x2 %0, %1, %2, %0;" : "+l"(d) : "l"(a), "l"(b));
}

// pair barrier: warps {wm, wm+4} (64 threads), ids 1..4
#define BARP(id) asm volatile("bar.sync %0, 64;" :: "r"(id) : "memory")

// ==================== Kernel 1: LSH hashing (fp32 f32x2) + fused fp16 prep ====================
// grid = BB * (SS/64) = 1024 CTAs, 256 threads.
__global__ __launch_bounds__(256, 2) void hash_kernel(const float* __restrict__ qk,
                                                      const float* __restrict__ v,
                                                      const float* __restrict__ rot) {
    extern __shared__ float sm[];
    float* qT  = sm;              // 64*68 floats
    float* big = sm + 64 * 68;    // max(64*260, 256*68) = 17408 floats

    const int blk  = blockIdx.x;
    const int b    = blk >> 6;
    const int t0   = (blk & 63) * 64;
    const int tid  = threadIdx.x;
    const int w    = tid >> 5, l = tid & 31;

    {
        const float4* rg = (const float4*)rot;
        for (int i4 = tid; i4 < 64 * 64; i4 += 256) {
            int f = i4 >> 6, o4 = i4 & 63;
            *(float4*)&big[f * 260 + o4 * 4] = rg[i4];
        }
    }
    // q tile load (transposed into qT) + fused prep: qs (log2-scaled), kh, vh
    for (int r = 0; r < 8; r++) {
        int i = w * 8 + r;
        size_t gi = (size_t)b * SS + t0 + i;
        float2 qv = ((const float2*)(qk + gi * DD))[l];
        qT[(2 * l) * 68 + i]     = qv.x;
        qT[(2 * l + 1) * 68 + i] = qv.y;
        float ssq = qv.x * qv.x + qv.y * qv.y;
#pragma unroll
        for (int o = 16; o; o >>= 1) ssq += __shfl_xor_sync(0xffffffffu, ssq, o);
        float nrm = sqrtf(ssq);
        float inv = 1.0f / fmaxf(nrm, 1e-12f);
        g_kh[gi * 32 + l] = __floats2half2_rn(qv.x * inv, qv.y * inv);
        if (l == 0) g_qs[gi] = 0.125f * 1.44269504f * nrm;   // includes log2(e)
        float2 vv = ((const float2*)(v + gi * DD))[l];
        g_vh[gi * 32 + l] = __floats2half2_rn(vv.x, vv.y);
    }
    __syncthreads();

    const int rt = tid >> 4, ct = tid & 15;
    unsigned long long acc2[4][8];
#pragma unroll
    for (int r = 0; r < 4; r++)
#pragma unroll
        for (int p = 0; p < 8; p++) acc2[r][p] = pack2(0.f, 0.f);

    const float4* qT4 = (const float4*)qT;   // stride 17
    const float4* rt4 = (const float4*)big;  // stride 65
#pragma unroll 4
    for (int f = 0; f < 64; f++) {
        float4 q = qT4[f * 17 + rt];
        unsigned long long qq[4];
        qq[0] = pack2(q.x, q.x); qq[1] = pack2(q.y, q.y);
        qq[2] = pack2(q.z, q.z); qq[3] = pack2(q.w, q.w);
#pragma unroll
        for (int g = 0; g < 4; g++) {
            float4 rv = rt4[f * 65 + g * 16 + ct];
            unsigned long long r0 = pack2(rv.x, rv.y);
            unsigned long long r1 = pack2(rv.z, rv.w);
#pragma unroll
            for (int r = 0; r < 4; r++) {
                fma2(acc2[r][g * 2],     qq[r], r0);
                fma2(acc2[r][g * 2 + 1], qq[r], r1);
            }
        }
    }
    float acc[4][16];
#pragma unroll
    for (int r = 0; r < 4; r++)
#pragma unroll
        for (int p = 0; p < 8; p++)
            unpack2(acc[r][p * 2], acc[r][p * 2 + 1], acc2[r][p]);
    __syncthreads();   // rot dead, reuse region as dsH[o][t] stride 68

    float* dsH = big;
#pragma unroll
    for (int g = 0; g < 4; g++)
#pragma unroll
        for (int c = 0; c < 4; c++) {
            int o = g * 64 + ct * 4 + c;
            *(float4*)&dsH[o * 68 + rt * 4] =
                make_float4(acc[0][g * 4 + c], acc[1][g * 4 + c], acc[2][g * 4 + c], acc[3][g * 4 + c]);
        }
    __syncthreads();

    for (int p = tid; p < 512; p += 256) {
        int t = p & 63, hh = p >> 6;
        const float* dv = &dsH[(hh * 32) * 68 + t];
        float best = dv[0];
        int bi = 0;
#pragma unroll
        for (int j = 1; j < 32; j++) { float vv = dv[j * 68];  if (vv > best) { best = vv; bi = j; } }
#pragma unroll
        for (int j = 0; j < 32; j++) { float vv = -dv[j * 68]; if (vv > best) { best = vv; bi = 32 + j; } }
        g_buckets[((size_t)(b * HH + hh)) * SS + t0 + t] = bi;
    }
}

// ==================== Kernel 2: stable counting sort per (b,h) ====================
__global__ __launch_bounds__(512) void sort_kernel() {
    __shared__ int hist[16][64];
    __shared__ int run[16][64];
    __shared__ int totals[64];
    __shared__ int bstart[64];

    const int bh  = blockIdx.x;
    const int* bk = g_buckets + (size_t)bh * SS;
    int* dst      = g_st + (size_t)bh * SS;
    const int tid = threadIdx.x, w = tid >> 5, l = tid & 31;

    for (int i = tid; i < 1024; i += 512) ((int*)hist)[i] = 0;
    __syncthreads();

    for (int r = 0; r < 8; r++) {
        int t = w * 256 + r * 32 + l;
        int vv = bk[t];
        unsigned mask = __match_any_sync(0xffffffffu, vv);
        if (l == (int)(__ffs(mask) - 1)) hist[w][vv] += __popc(mask);
        __syncwarp();
    }
    __syncthreads();

    if (tid < 64) {
        int s = 0;
        for (int ww = 0; ww < 16; ww++) { int tmp = hist[ww][tid]; hist[ww][tid] = s; s += tmp; }
        totals[tid] = s;
    }
    __syncthreads();
    if (tid == 0) {
        int s = 0;
        for (int vv = 0; vv < 64; vv++) { bstart[vv] = s; s += totals[vv]; }
    }
    __syncthreads();
    for (int i = tid; i < 1024; i += 512) {
        int ww = i >> 6, vv = i & 63;
        run[ww][vv] = bstart[vv] + hist[ww][vv];
    }
    __syncthreads();

    for (int r = 0; r < 8; r++) {
        int t = w * 256 + r * 32 + l;
        int vv = bk[t];
        unsigned mask = __match_any_sync(0xffffffffu, vv);
        int rank = __popc(mask & ((1u << l) - 1u));
        int base = run[w][vv];
        __syncwarp();
        if (l == (int)(__ffs(mask) - 1)) run[w][vv] = base + __popc(mask);
        __syncwarp();
        dst[base + rank] = t;
    }
}

// ==================== Kernel 3: chunked attention (Gram, split K/V groups, exp2 softmax) ====================
// grid = BB*CHK = 8192 CTAs, 256 threads (8 warps), 47872B smem, 4 CTAs/SM.
// Smem: tki[128]@0 | qs[64]f@512 | stats[256]f@768 | Ksm 128x144B@1792 | Vsm 128x144B@20224 | Dxh 64x72h@38656
__global__ __launch_bounds__(256, 4) void attn_kernel() {
    extern __shared__ char smc[];
    int*    tki   = (int*)smc;
    float*  qs_sm = (float*)(smc + 512);
    float*  stats = (float*)(smc + 768);
    __half* Ksm   = (__half*)(smc + 1792);
    __half* Vsm   = (__half*)(smc + 20224);
    __half* Dxh   = (__half*)(smc + 38656);

    const int blk = blockIdx.x;
    const int b = blk >> 9, c = blk & 511;
    const int h  = c >> 6;
    const int cp = (c + 511) & 511;
    const int hp = cp >> 6;
    const int tid = threadIdx.x, w = tid >> 5, l = tid & 31;
    const int gID = l >> 2, tig = l & 3;
    const int wm = w & 3, wn = w >> 2;
    const int arow = wm * 16 + gID;

    if (tid < 64) {
        int t = g_st[((size_t)(b * HH + h)) * SS + (c & 63) * 64 + tid];
        tki[tid] = t;
        qs_sm[tid] = g_qs[(size_t)b * SS + t];
    } else if (tid < 128) {
        int i = tid - 64;
        tki[64 + i] = g_st[((size_t)(b * HH + hp)) * SS + (cp & 63) * 64 + i];
    }
    __syncthreads();

    // ---- gather K (group 0) then V (group 1) via cp.async
    {
        unsigned k_u32 = (unsigned)__cvta_generic_to_shared(Ksm);
        unsigned v_u32 = (unsigned)__cvta_generic_to_shared(Vsm);
        const char* kh = (const char*)g_kh + (size_t)b * SS * 128;
        const char* vh = (const char*)g_vh + (size_t)b * SS * 128;
#pragma unroll
        for (int it = 0; it < 4; it++) {           // 128 k rows
            int slot = tid + it * 256;
            int row = slot >> 3, ch = slot & 7;
            cp16(k_u32 + row * 144 + ch * 16, kh + (size_t)tki[row] * 128 + ch * 16);
        }
        asm volatile("cp.async.commit_group;" ::: "memory");
#pragma unroll
        for (int it = 0; it < 4; it++) {           // 128 v rows
            int slot = tid + it * 256;
            int row = slot >> 3, ch = slot & 7;
            cp16(v_u32 + row * 144 + ch * 16, vh + (size_t)tki[row] * 128 + ch * 16);
        }
        asm volatile("cp.async.commit_group;" ::: "memory");
        asm volatile("cp.async.wait_group 1;" ::: "memory");   // K complete
    }
    __syncthreads();   // K visible to all threads

    // ---- ldmatrix lane addressing (A rows come from Ksm rows 0..63)
    const int lrow = (l & 7) + ((l >> 3) & 1) * 8;
    const int lcsh = ((l >> 4) & 1) * 16;
    const unsigned ksm_u32 = (unsigned)__cvta_generic_to_shared(Ksm);
    const unsigned afrag  = ksm_u32 + (wm * 16 + lrow) * 144 + lcsh;
    const unsigned kfragb = ksm_u32 + (wn * 64 + lrow) * 144 + lcsh;
    const unsigned vfragb = (unsigned)__cvta_generic_to_shared(Vsm) + (wn * 64 + lrow) * 144 + lcsh;

    // ---- Gram K̂K̂ᵀ via fp16 mma (K=64: 4 k16 steps; 8 n-tiles as 4 pairs)
    float cqk[8][4];
#pragma unroll
    for (int nt = 0; nt < 8; nt++)
#pragma unroll
        for (int r = 0; r < 4; r++) cqk[nt][r] = 0.f;

#pragma unroll
    for (int s = 0; s < 4; s++) {
        unsigned a0, a1, a2, a3;
        ldsm4(a0, a1, a2, a3, afrag + s * 32);
#pragma unroll
        for (int p = 0; p < 4; p++) {
            unsigned b00, b01, b10, b11;
            ldsm4(b00, b01, b10, b11, kfragb + p * 16 * 144 + s * 32);
            mma_f16(cqk[2 * p],     a0, a1, a2, a3, b00, b10);
            mma_f16(cqk[2 * p + 1], a0, a1, a2, a3, b01, b11);
        }
    }

    // ---- per-query-row scale (log2-domain dots), then self-mask
    const float qs0 = qs_sm[arow], qs1 = qs_sm[arow + 8];
    const int tq0 = tki[arow], tq1 = tki[arow + 8];
#pragma unroll
    for (int nt = 0; nt < 8; nt++) {
        cqk[nt][0] *= qs0; cqk[nt][1] *= qs0;
        cqk[nt][2] *= qs1; cqk[nt][3] *= qs1;
        int2 kk = *(int2*)&tki[wn * 64 + nt * 8 + 2 * tig];
        if (kk.x == tq0) cqk[nt][0] = -5e4f;
        if (kk.y == tq0) cqk[nt][1] = -5e4f;
        if (kk.x == tq1) cqk[nt][2] = -5e4f;
        if (kk.y == tq1) cqk[nt][3] = -5e4f;
    }

    // ---- register softmax (base-2): per-row partial (m, s)
    float m0 = -3.4e38f, m1 = -3.4e38f;
#pragma unroll
    for (int nt = 0; nt < 8; nt++) {
        m0 = fmaxf(m0, fmaxf(cqk[nt][0], cqk[nt][1]));
        m1 = fmaxf(m1, fmaxf(cqk[nt][2], cqk[nt][3]));
    }
    m0 = fmaxf(m0, __shfl_xor_sync(0xffffffffu, m0, 1));
    m0 = fmaxf(m0, __shfl_xor_sync(0xffffffffu, m0, 2));
    m1 = fmaxf(m1, __shfl_xor_sync(0xffffffffu, m1, 1));
    m1 = fmaxf(m1, __shfl_xor_sync(0xffffffffu, m1, 2));
    float s0 = 0.f, s1 = 0.f;
#pragma unroll
    for (int nt = 0; nt < 8; nt++) {
        float e0 = ex2f(cqk[nt][0] - m0), e1 = ex2f(cqk[nt][1] - m0);
        float e2 = ex2f(cqk[nt][2] - m1), e3 = ex2f(cqk[nt][3] - m1);
        cqk[nt][0] = e0; cqk[nt][1] = e1; cqk[nt][2] = e2; cqk[nt][3] = e3;
        s0 += e0 + e1; s1 += e2 + e3;
    }
    s0 += __shfl_xor_sync(0xffffffffu, s0, 1);
    s0 += __shfl_xor_sync(0xffffffffu, s0, 2);
    s1 += __shfl_xor_sync(0xffffffffu, s1, 1);
    s1 += __shfl_xor_sync(0xffffffffu, s1, 2);
    if (tig == 0) {
        stats[(wn * 64 + arow) * 2]         = m0;
        stats[(wn * 64 + arow) * 2 + 1]     = s0;
        stats[(wn * 64 + arow + 8) * 2]     = m1;
        stats[(wn * 64 + arow + 8) * 2 + 1] = s1;
    }
    asm volatile("cp.async.wait_group 0;" ::: "memory");   // V complete (this thread)
    __syncthreads();   // stats exchange + V visibility, one full barrier

    float om0 = stats[((wn ^ 1) * 64 + arow) * 2];
    float os0 = stats[((wn ^ 1) * 64 + arow) * 2 + 1];
    float om1 = stats[((wn ^ 1) * 64 + arow + 8) * 2];
    float os1 = stats[((wn ^ 1) * 64 + arow + 8) * 2 + 1];
    float M0 = fmaxf(m0, om0), M1 = fmaxf(m1, om1);
    float S0 = s0 * ex2f(m0 - M0) + os0 * ex2f(om0 - M0);
    float S1 = s1 * ex2f(m1 - M1) + os1 * ex2f(om1 - M1);
    float sc0 = ex2f(m0 - M0) / S0;
    float sc1 = ex2f(m1 - M1) / S1;
    if (wn == 0 && tig == 0) {
        g_lse[((size_t)b * SS + tq0) * HH + h] = (M0 + __log2f(S0)) * 0.69314718f;
        g_lse[((size_t)b * SS + tq1) * HH + h] = (M1 + __log2f(S1)) * 0.69314718f;
    }

    // ---- convert ALL PV A-fragments up front (cqk dies here)
    unsigned af[4][4];
#pragma unroll
    for (int s = 0; s < 4; s++) {
        af[s][0] = h2_u32(__floats2half2_rn(cqk[2 * s][0] * sc0, cqk[2 * s][1] * sc0));
        af[s][1] = h2_u32(__floats2half2_rn(cqk[2 * s][2] * sc1, cqk[2 * s][3] * sc1));
        af[s][2] = h2_u32(__floats2half2_rn(cqk[2 * s + 1][0] * sc0, cqk[2 * s + 1][1] * sc0));
        af[s][3] = h2_u32(__floats2half2_rn(cqk[2 * s + 1][2] * sc1, cqk[2 * s + 1][3] * sc1));
    }

    // ---- P @ V over this warp's 64-key half; B via ldmatrix.trans from row-major Vsm
    float oacc[8][4];
#pragma unroll
    for (int ft = 0; ft < 8; ft++)
#pragma unroll
        for (int r = 0; r < 4; r++) oacc[ft][r] = 0.f;

#pragma unroll
    for (int s = 0; s < 4; s++) {
#pragma unroll
        for (int t = 0; t < 4; t++) {
            unsigned r0, r1, r2, r3;
            ldsm4t(r0, r1, r2, r3, vfragb + s * 16 * 144 + t * 32);
            mma_f16(oacc[2 * t],     af[s][0], af[s][1], af[s][2], af[s][3], r0, r1);
            mma_f16(oacc[2 * t + 1], af[s][0], af[s][1], af[s][2], af[s][3], r2, r3);
        }
    }

    // ---- sum wn partials via fp16 Dxh (pair barrier), store fp16 outputs [b][t][h]
    if (wn == 1) {
#pragma unroll
        for (int ft = 0; ft < 8; ft++) {
            *(__half2*)&Dxh[arow * 72 + ft * 8 + 2 * tig]       = __floats2half2_rn(oacc[ft][0], oacc[ft][1]);
            *(__half2*)&Dxh[(arow + 8) * 72 + ft * 8 + 2 * tig] = __floats2half2_rn(oacc[ft][2], oacc[ft][3]);
        }
    }
    BARP(1 + wm);
    if (wn == 0) {
        __half2* o0 = g_o + (((size_t)b * SS + tq0) * HH + h) * 32;
        __half2* o1 = g_o + (((size_t)b * SS + tq1) * HH + h) * 32;
#pragma unroll
        for (int ft = 0; ft < 8; ft++) {
            float2 d0 = __half22float2(*(__half2*)&Dxh[arow * 72 + ft * 8 + 2 * tig]);
            float2 d1 = __half22float2(*(__half2*)&Dxh[(arow + 8) * 72 + ft * 8 + 2 * tig]);
            o0[ft * 4 + tig] = __floats2half2_rn(oacc[ft][0] + d0.x, oacc[ft][1] + d0.y);
            o1[ft * 4 + tig] = __floats2half2_rn(oacc[ft][2] + d1.x, oacc[ft][3] + d1.y);
        }
    }
}

// ==================== Kernel 4: combine hash rounds ([b][t][h] contiguous) ====================
__global__ __launch_bounds__(256) void combine_kernel(float* __restrict__ out) {
    const int gw = (blockIdx.x * 256 + threadIdx.x) >> 5;
    const int l  = threadIdx.x & 31;
    const int b  = gw >> 12, t = gw & (SS - 1);

    const float* lsep = g_lse + ((size_t)b * SS + t) * HH;
    float lg[HH];
#pragma unroll
    for (int hh = 0; hh < HH; hh++) lg[hh] = lsep[hh];
    float m = lg[0];
#pragma unroll
    for (int hh = 1; hh < HH; hh++) m = fmaxf(m, lg[hh]);
    float wv[HH];
    float wsum = 0.f;
#pragma unroll
    for (int hh = 0; hh < HH; hh++) { wv[hh] = __expf(lg[hh] - m); wsum += wv[hh]; }
    float inv = 1.0f / wsum;

    const __half2* ob = g_o + ((size_t)b * SS + t) * HH * 32;
    float2 accv = make_float2(0.f, 0.f);
#pragma unroll
    for (int hh = 0; hh < HH; hh++) {
        float2 ov = __half22float2(ob[hh * 32 + l]);
        float wgt = wv[hh] * inv;
        accv.x += wgt * ov.x;
        accv.y += wgt * ov.y;
    }
    ((float2*)(out + ((size_t)b * SS + t) * DD))[l] = accv;
}

// ==================== launch ====================
extern "C" void kernel_launch(void* const* d_in, const int* in_sizes, int n_in,
                              void* d_out, int out_size) {
    const float* qk  = (const float*)d_in[0];
    const float* v   = (const float*)d_in[1];
    const float* rot = (const float*)d_in[2];
    float* out = (float*)d_out;

    (void)in_sizes; (void)n_in; (void)out_size;

    const int hash_smem = 87040;   // 64*68*4 + 256*68*4
    const int attn_smem = 47872;   // tki/qs/stats + Ksm + Vsm + Dxh
    cudaFuncSetAttribute(hash_kernel, cudaFuncAttributeMaxDynamicSharedMemorySize, hash_smem);
    cudaFuncSetAttribute(attn_kernel, cudaFuncAttributeMaxDynamicSharedMemorySize, attn_smem);

    hash_kernel<<<BB * (SS / 64), 256, hash_smem>>>(qk, v, rot);
    sort_kernel<<<BB * HH, 512>>>();
    attn_kernel<<<BB * CHK, 256, attn_smem>>>();
    combine_kernel<<<(BB * SS) / 8, 256>>>(out);
}